// round 1
// baseline (speedup 1.0000x reference)
#include <cuda_runtime.h>
#include <cuda_bf16.h>
#include <math.h>

// Problem constants
#define BB 8
#define SS 2048
#define DD 512   // D_IN == D_EMB == 512

// Scratch in device globals (no runtime allocation allowed)
__device__ float g_Q[BB * SS * DD];
__device__ float g_K[BB * SS * DD];
__device__ float g_V[BB * SS * DD];
__device__ float g_S[(long long)BB * SS * SS];   // 128 MB scores

// ---------------------------------------------------------------------------
// Generic 128x128 tiled SIMT fp32 GEMM.
//   C[M,N] = alpha * A[M,K] * op(B) + bias
//   B_NK = true  : B is [N,K] row-major (dot over K rows of B)  -> C = A * B^T
//   B_NK = false : B is [K,N] row-major                         -> C = A * B
// 256 threads, 8x8 accumulators per thread, K tile of 8.
// blockIdx.z selects batch via strides sA/sB/sC.
// ---------------------------------------------------------------------------
template <bool B_NK>
__global__ void __launch_bounds__(256)
gemm128(const float* __restrict__ Ab, const float* __restrict__ Bb,
        const float* __restrict__ bias, float* __restrict__ Cb,
        int M, int N, int K, float alpha,
        long long sA, long long sB, long long sC)
{
    const float* A = Ab + (long long)blockIdx.z * sA;
    const float* B = Bb + (long long)blockIdx.z * sB;
    float*       C = Cb + (long long)blockIdx.z * sC;

    __shared__ float As[8][132];
    __shared__ float Bs[8][132];

    const int tid = threadIdx.x;
    const int tx  = tid & 15;       // 0..15 -> column group
    const int ty  = tid >> 4;       // 0..15 -> row group
    const int row0 = blockIdx.y * 128;
    const int col0 = blockIdx.x * 128;

    // A-load indices: 128 rows x 8 k, float4 along k (2 threads per row)
    const int am = tid >> 1;            // 0..127
    const int ak = (tid & 1) * 4;       // 0 or 4

    float acc[8][8];
#pragma unroll
    for (int i = 0; i < 8; i++)
#pragma unroll
        for (int j = 0; j < 8; j++) acc[i][j] = 0.0f;

    for (int k0 = 0; k0 < K; k0 += 8) {
        // ---- load A tile (transposed into As[k][m]) ----
        {
            const float4 a4 = *(const float4*)(A + (long long)(row0 + am) * K + k0 + ak);
            As[ak + 0][am] = a4.x;
            As[ak + 1][am] = a4.y;
            As[ak + 2][am] = a4.z;
            As[ak + 3][am] = a4.w;
        }
        // ---- load B tile ----
        if (B_NK) {
            const int bn = tid >> 1;
            const int bk = (tid & 1) * 4;
            const float4 b4 = *(const float4*)(B + (long long)(col0 + bn) * K + k0 + bk);
            Bs[bk + 0][bn] = b4.x;
            Bs[bk + 1][bn] = b4.y;
            Bs[bk + 2][bn] = b4.z;
            Bs[bk + 3][bn] = b4.w;
        } else {
            const int kk = tid >> 5;            // 0..7
            const int n4 = (tid & 31) * 4;      // 0..124
            const float4 b4 = *(const float4*)(B + (long long)(k0 + kk) * N + col0 + n4);
            *(float4*)&Bs[kk][n4] = b4;
        }
        __syncthreads();

#pragma unroll
        for (int kk = 0; kk < 8; kk++) {
            float a[8], b[8];
            *(float4*)&a[0] = *(const float4*)&As[kk][ty * 4];
            *(float4*)&a[4] = *(const float4*)&As[kk][64 + ty * 4];
            *(float4*)&b[0] = *(const float4*)&Bs[kk][tx * 4];
            *(float4*)&b[4] = *(const float4*)&Bs[kk][64 + tx * 4];
#pragma unroll
            for (int i = 0; i < 8; i++)
#pragma unroll
                for (int j = 0; j < 8; j++)
                    acc[i][j] = fmaf(a[i], b[j], acc[i][j]);
        }
        __syncthreads();
    }

    // ---- epilogue: scale, bias, store (float4) ----
#pragma unroll
    for (int ig = 0; ig < 2; ig++) {
#pragma unroll
        for (int ir = 0; ir < 4; ir++) {
            const int i = row0 + ig * 64 + ty * 4 + ir;
#pragma unroll
            for (int jg = 0; jg < 2; jg++) {
                const int j = col0 + jg * 64 + tx * 4;
                float4 r;
                r.x = acc[ig * 4 + ir][jg * 4 + 0] * alpha;
                r.y = acc[ig * 4 + ir][jg * 4 + 1] * alpha;
                r.z = acc[ig * 4 + ir][jg * 4 + 2] * alpha;
                r.w = acc[ig * 4 + ir][jg * 4 + 3] * alpha;
                if (bias != nullptr) {
                    const float4 bv = *(const float4*)(bias + j);
                    r.x += bv.x; r.y += bv.y; r.z += bv.z; r.w += bv.w;
                }
                *(float4*)(C + (long long)i * N + j) = r;
            }
        }
    }
}

// ---------------------------------------------------------------------------
// Row softmax over 2048 columns, in place. One block (256 threads) per row.
// ---------------------------------------------------------------------------
__global__ void __launch_bounds__(256)
softmax2048(float* __restrict__ S)
{
    float* row = S + (long long)blockIdx.x * SS;
    const int t = threadIdx.x;

    float v[8];
    float m = -INFINITY;
#pragma unroll
    for (int i = 0; i < 8; i++) {
        v[i] = row[t + i * 256];
        m = fmaxf(m, v[i]);
    }

    __shared__ float red[8];
    // warp max
#pragma unroll
    for (int o = 16; o > 0; o >>= 1)
        m = fmaxf(m, __shfl_xor_sync(0xffffffffu, m, o));
    if ((t & 31) == 0) red[t >> 5] = m;
    __syncthreads();
    if (t < 32) {
        float mm = (t < 8) ? red[t] : -INFINITY;
#pragma unroll
        for (int o = 4; o > 0; o >>= 1)
            mm = fmaxf(mm, __shfl_xor_sync(0xffffffffu, mm, o));
        if (t == 0) red[0] = mm;
    }
    __syncthreads();
    m = red[0];
    __syncthreads();

    float sum = 0.0f;
#pragma unroll
    for (int i = 0; i < 8; i++) {
        v[i] = __expf(v[i] - m);
        sum += v[i];
    }
#pragma unroll
    for (int o = 16; o > 0; o >>= 1)
        sum += __shfl_xor_sync(0xffffffffu, sum, o);
    if ((t & 31) == 0) red[t >> 5] = sum;
    __syncthreads();
    if (t < 32) {
        float ss = (t < 8) ? red[t] : 0.0f;
#pragma unroll
        for (int o = 4; o > 0; o >>= 1)
            ss += __shfl_xor_sync(0xffffffffu, ss, o);
        if (t == 0) red[0] = ss;
    }
    __syncthreads();
    const float inv = 1.0f / red[0];

#pragma unroll
    for (int i = 0; i < 8; i++)
        row[t + i * 256] = v[i] * inv;
}

// ---------------------------------------------------------------------------
extern "C" void kernel_launch(void* const* d_in, const int* in_sizes, int n_in,
                              void* d_out, int out_size)
{
    (void)in_sizes; (void)n_in; (void)out_size;

    const float* x  = (const float*)d_in[0];
    const float* Wq = (const float*)d_in[1];
    const float* bq = (const float*)d_in[2];
    const float* Wk = (const float*)d_in[3];
    const float* bk = (const float*)d_in[4];
    const float* Wv = (const float*)d_in[5];
    const float* bv = (const float*)d_in[6];
    float* out = (float*)d_out;

    float *Q, *K, *V, *Sc;
    cudaGetSymbolAddress((void**)&Q,  g_Q);
    cudaGetSymbolAddress((void**)&K,  g_K);
    cudaGetSymbolAddress((void**)&V,  g_V);
    cudaGetSymbolAddress((void**)&Sc, g_S);

    const int M   = BB * SS;                  // 16384
    const float scale = 1.0f / sqrtf((float)DD);

    dim3 blk(256);

    // 1) Projections: Q/K/V = x @ W + b   (M=16384, N=K=512)
    {
        dim3 grid(DD / 128, M / 128, 1);
        gemm128<false><<<grid, blk>>>(x, Wq, bq, Q, M, DD, DD, 1.0f, 0, 0, 0);
        gemm128<false><<<grid, blk>>>(x, Wk, bk, K, M, DD, DD, 1.0f, 0, 0, 0);
        gemm128<false><<<grid, blk>>>(x, Wv, bv, V, M, DD, DD, 1.0f, 0, 0, 0);
    }

    // 2) Scores = scale * Q @ K^T per batch  (M=N=2048, K=512)
    {
        dim3 grid(SS / 128, SS / 128, BB);
        gemm128<true><<<grid, blk>>>(Q, K, nullptr, Sc,
                                     SS, SS, DD, scale,
                                     (long long)SS * DD, (long long)SS * DD,
                                     (long long)SS * SS);
    }

    // 3) Row softmax in place
    softmax2048<<<BB * SS, blk>>>(Sc);

    // 4) out = P @ V per batch  (M=2048, N=512, K=2048)
    {
        dim3 grid(DD / 128, SS / 128, BB);
        gemm128<false><<<grid, blk>>>(Sc, V, nullptr, out,
                                      SS, DD, SS, 1.0f,
                                      (long long)SS * SS, (long long)SS * DD,
                                      (long long)SS * DD);
    }
}

// round 3
// speedup vs baseline: 2.1722x; 2.1722x over previous
#include <cuda_runtime.h>
#include <cuda_fp16.h>
#include <math.h>
#include <stdint.h>

#define BB 8
#define SS 2048
#define DD 512
#define MTOT (BB*SS)

// ---------------- device scratch (no runtime allocation allowed) ------------
__device__ __half g_xh[MTOT*DD], g_xl[MTOT*DD];
__device__ __half g_Wth[3][DD*DD], g_Wtl[3][DD*DD];
__device__ __half g_Qh[MTOT*DD], g_Ql[MTOT*DD];
__device__ __half g_Kh[MTOT*DD], g_Kl[MTOT*DD];
__device__ float  g_Vf[MTOT*DD];
__device__ __half g_Vth[MTOT*DD], g_Vtl[MTOT*DD];
__device__ float  g_S [(long long)BB*SS*SS];
__device__ __half g_Ph[(long long)BB*SS*SS], g_Pl[(long long)BB*SS*SS];

// ---------------- helpers ----------------------------------------------------
__device__ __forceinline__ uint32_t smem_u32(const void* p){
    uint32_t a;
    asm("{ .reg .u64 t; cvta.to.shared.u64 t, %1; cvt.u32.u64 %0, t; }" : "=r"(a) : "l"(p));
    return a;
}
__device__ __forceinline__ void cpa16(uint32_t dst, const void* src){
    asm volatile("cp.async.cg.shared.global [%0], [%1], 16;" :: "r"(dst), "l"(src));
}
__device__ __forceinline__ void cpa_commit(){ asm volatile("cp.async.commit_group;"); }
template<int N> __device__ __forceinline__ void cpa_wait(){
    asm volatile("cp.async.wait_group %0;" :: "n"(N));
}
__device__ __forceinline__ void ldm_x4(uint32_t* r, uint32_t addr){
    asm volatile("ldmatrix.sync.aligned.m8n8.x4.shared.b16 {%0,%1,%2,%3}, [%4];"
        : "=r"(r[0]), "=r"(r[1]), "=r"(r[2]), "=r"(r[3]) : "r"(addr));
}
__device__ __forceinline__ void mma16816(float* d, const uint32_t* a, uint32_t b0, uint32_t b1){
    asm volatile("mma.sync.aligned.m16n8k16.row.col.f32.f16.f16.f32 "
        "{%0,%1,%2,%3},{%4,%5,%6,%7},{%8,%9},{%0,%1,%2,%3};"
        : "+f"(d[0]), "+f"(d[1]), "+f"(d[2]), "+f"(d[3])
        : "r"(a[0]), "r"(a[1]), "r"(a[2]), "r"(a[3]), "r"(b0), "r"(b1));
}

// ---------------- smem layout -------------------------------------------------
// Per stage: Ah, Al, Bh, Bl blocks of 128 rows x 80 bytes (64B data + 16B pad).
// 80B pitch => conflict-free ldmatrix (8-row phases hit 8 distinct bank groups).
#define PITCH   80
#define MATB    (128*PITCH)      // 10240
#define STAGEB  (4*MATB)         // 40960
#define SMEMB   (2*STAGEB)       // 81920

// ---------------- split-fp16 tensor-core GEMM ---------------------------------
// C[128x128 tile] = (Ah+Al) * (Bh+Bl)^T, A:[M,K] K-major, B:[N,K] K-major.
// 3-term: Ah*Bh + Ah*Bl + Al*Bh. 256 threads, 8 warps, warp tile 64x32.
// EPI 0: Cf = alpha*D + bias (fp32).  EPI 1: (Ch,Cl) = split(D + bias) (fp16 hi/lo).
template<int EPI>
__global__ void __launch_bounds__(256)
gemm_mma(const __half* __restrict__ Ah, const __half* __restrict__ Al,
         const __half* __restrict__ Bh, const __half* __restrict__ Bl,
         const float* __restrict__ bias,
         float* __restrict__ Cf, __half* __restrict__ Ch, __half* __restrict__ Cl,
         int N, int K, float alpha,
         long long sA, long long sB, long long sC)
{
    extern __shared__ char smem[];
    const uint32_t sb = smem_u32(smem);
    const int tid = threadIdx.x;
    const int wid = tid >> 5, lane = tid & 31;
    const int wr = wid >> 2, wc = wid & 3;          // warp grid 2x4
    const int wm0 = wr * 64, wn0 = wc * 32;

    const int row0 = blockIdx.y << 7, col0 = blockIdx.x << 7;
    const long long zA = (long long)blockIdx.z * sA;
    const long long zB = (long long)blockIdx.z * sB;
    const long long zC = (long long)blockIdx.z * sC;

    const __half* gsrc[4] = { Ah + zA + (long long)row0 * K,
                              Al + zA + (long long)row0 * K,
                              Bh + zB + (long long)col0 * K,
                              Bl + zB + (long long)col0 * K };

    // loader indices: 512 (row,unit) slots per matrix, 2 iters of 256 threads
    const int lrow0 = tid >> 2;          // slot row for it=0 (0..63)
    const int lu    = tid & 3;           // 16B unit 0..3

    float acc[4][4][4];
#pragma unroll
    for (int i = 0; i < 4; i++)
#pragma unroll
        for (int j = 0; j < 4; j++)
#pragma unroll
            for (int q = 0; q < 4; q++) acc[i][j][q] = 0.0f;

    const int NC = K >> 5;   // chunks of 32

    auto load_chunk = [&](int stage, int kc) {
        const uint32_t sdst = sb + stage * STAGEB;
#pragma unroll
        for (int m = 0; m < 4; m++) {
            const __half* g = gsrc[m] + kc * 32;
#pragma unroll
            for (int it = 0; it < 2; it++) {
                const int row = lrow0 + it * 64;
                cpa16(sdst + m * MATB + row * PITCH + lu * 16,
                      g + (long long)row * K + lu * 8);
            }
        }
    };

    load_chunk(0, 0);
    cpa_commit();

    for (int kc = 0; kc < NC; kc++) {
        const int s = kc & 1;
        if (kc + 1 < NC) { load_chunk(s ^ 1, kc + 1); cpa_commit(); cpa_wait<1>(); }
        else             { cpa_wait<0>(); }
        __syncthreads();

        const uint32_t sAh = sb + s * STAGEB;
        const uint32_t sAl = sAh + MATB;
        const uint32_t sBh = sAh + 2 * MATB;
        const uint32_t sBl = sAh + 3 * MATB;

        const int lr = lane & 15;            // ldmatrix row-in-tile
        const int lc = (lane >> 4) * 16;     // ldmatrix col byte offset (k8 select)

#pragma unroll
        for (int k16 = 0; k16 < 2; k16++) {
            const uint32_t kb = k16 * 32 + lc;
            uint32_t ah[4][4], al[4][4], bh[2][4], bl[2][4];
#pragma unroll
            for (int i = 0; i < 4; i++) {
                const uint32_t ro = (uint32_t)(wm0 + i * 16 + lr) * PITCH + kb;
                ldm_x4(ah[i], sAh + ro);
                ldm_x4(al[i], sAl + ro);
            }
#pragma unroll
            for (int jj = 0; jj < 2; jj++) {
                const uint32_t ro = (uint32_t)(wn0 + jj * 16 + lr) * PITCH + kb;
                ldm_x4(bh[jj], sBh + ro);
                ldm_x4(bl[jj], sBl + ro);
            }
#pragma unroll
            for (int i = 0; i < 4; i++) {
#pragma unroll
                for (int j = 0; j < 4; j++) {
                    const int jj = j >> 1, sel = j & 1;
                    mma16816(acc[i][j], ah[i], bh[jj][sel], bh[jj][sel + 2]);
                    mma16816(acc[i][j], ah[i], bl[jj][sel], bl[jj][sel + 2]);
                    mma16816(acc[i][j], al[i], bh[jj][sel], bh[jj][sel + 2]);
                }
            }
        }
        __syncthreads();
    }

    // ---------------- epilogue ----------------
    const int er = lane >> 2;            // 0..7
    const int ec = (lane & 3) * 2;       // 0,2,4,6
#pragma unroll
    for (int i = 0; i < 4; i++) {
#pragma unroll
        for (int j = 0; j < 4; j++) {
            const int col = col0 + wn0 + j * 8 + ec;
#pragma unroll
            for (int half_m = 0; half_m < 2; half_m++) {
                const int row = row0 + wm0 + i * 16 + er + half_m * 8;
                const float d0 = acc[i][j][half_m * 2 + 0];
                const float d1 = acc[i][j][half_m * 2 + 1];
                if (EPI == 0) {
                    float2 v;
                    v.x = d0 * alpha; v.y = d1 * alpha;
                    if (bias) { v.x += bias[col]; v.y += bias[col + 1]; }
                    *(float2*)(Cf + zC + (long long)row * N + col) = v;
                } else {
                    float f0 = d0 + bias[col];
                    float f1 = d1 + bias[col + 1];
                    __half h0 = __float2half_rn(f0), h1 = __float2half_rn(f1);
                    __half l0 = __float2half_rn(f0 - __half2float(h0));
                    __half l1 = __float2half_rn(f1 - __half2float(h1));
                    *(__half2*)(Ch + zC + (long long)row * N + col) = __halves2half2(h0, h1);
                    *(__half2*)(Cl + zC + (long long)row * N + col) = __halves2half2(l0, l1);
                }
            }
        }
    }
}

// ---------------- elementwise split fp32 -> (hi,lo) fp16 ---------------------
__global__ void __launch_bounds__(256)
split_f32(const float* __restrict__ s, __half* __restrict__ h, __half* __restrict__ l, int n4)
{
    int i = blockIdx.x * 256 + threadIdx.x;
    if (i >= n4) return;
    float4 v = ((const float4*)s)[i];
    float f[4] = {v.x, v.y, v.z, v.w};
    __half hh[4], ll[4];
#pragma unroll
    for (int j = 0; j < 4; j++) {
        hh[j] = __float2half_rn(f[j]);
        ll[j] = __float2half_rn(f[j] - __half2float(hh[j]));
    }
    *(__half2*)(h + 4*i)     = __halves2half2(hh[0], hh[1]);
    *(__half2*)(h + 4*i + 2) = __halves2half2(hh[2], hh[3]);
    *(__half2*)(l + 4*i)     = __halves2half2(ll[0], ll[1]);
    *(__half2*)(l + 4*i + 2) = __halves2half2(ll[2], ll[3]);
}

// ---------------- transpose + split: src fp32 [R,C] -> dst (hi,lo) [C,R] -----
__global__ void __launch_bounds__(256)
transpose_split(const float* __restrict__ src, __half* __restrict__ dh, __half* __restrict__ dl,
                int R, int C, long long sS, long long sD)
{
    __shared__ float t[32][33];
    const float* S = src + (long long)blockIdx.z * sS;
    __half* DH = dh + (long long)blockIdx.z * sD;
    __half* DL = dl + (long long)blockIdx.z * sD;
    const int c0 = blockIdx.x * 32, r0 = blockIdx.y * 32;
    const int tx = threadIdx.x, ty = threadIdx.y;   // (32, 8)
#pragma unroll
    for (int k = 0; k < 4; k++)
        t[ty + 8*k][tx] = S[(long long)(r0 + ty + 8*k) * C + c0 + tx];
    __syncthreads();
#pragma unroll
    for (int k = 0; k < 4; k++) {
        float f = t[tx][ty + 8*k];
        __half h = __float2half_rn(f);
        __half l = __float2half_rn(f - __half2float(h));
        long long o = (long long)(c0 + ty + 8*k) * R + r0 + tx;
        DH[o] = h; DL[o] = l;
    }
}

// ---------------- row softmax (2048 cols), fp32 in -> split fp16 out ----------
__global__ void __launch_bounds__(256)
softmax2048(const float* __restrict__ S, __half* __restrict__ Ph, __half* __restrict__ Pl)
{
    const long long rb = (long long)blockIdx.x * SS;
    const int t = threadIdx.x;
    float v[8];
    float m = -INFINITY;
#pragma unroll
    for (int i = 0; i < 8; i++) { v[i] = S[rb + t + i*256]; m = fmaxf(m, v[i]); }

    __shared__ float red[8];
#pragma unroll
    for (int o = 16; o > 0; o >>= 1) m = fmaxf(m, __shfl_xor_sync(0xffffffffu, m, o));
    if ((t & 31) == 0) red[t >> 5] = m;
    __syncthreads();
    if (t < 32) {
        float mm = (t < 8) ? red[t] : -INFINITY;
#pragma unroll
        for (int o = 4; o > 0; o >>= 1) mm = fmaxf(mm, __shfl_xor_sync(0xffffffffu, mm, o));
        if (t == 0) red[0] = mm;
    }
    __syncthreads();
    m = red[0];
    __syncthreads();

    float sum = 0.0f;
#pragma unroll
    for (int i = 0; i < 8; i++) { v[i] = __expf(v[i] - m); sum += v[i]; }
#pragma unroll
    for (int o = 16; o > 0; o >>= 1) sum += __shfl_xor_sync(0xffffffffu, sum, o);
    if ((t & 31) == 0) red[t >> 5] = sum;
    __syncthreads();
    if (t < 32) {
        float ss = (t < 8) ? red[t] : 0.0f;
#pragma unroll
        for (int o = 4; o > 0; o >>= 1) ss += __shfl_xor_sync(0xffffffffu, ss, o);
        if (t == 0) red[0] = ss;
    }
    __syncthreads();
    const float inv = 1.0f / red[0];

#pragma unroll
    for (int i = 0; i < 8; i++) {
        float p = v[i] * inv;
        __half h = __float2half_rn(p);
        __half l = __float2half_rn(p - __half2float(h));
        Ph[rb + t + i*256] = h;
        Pl[rb + t + i*256] = l;
    }
}

// -----------------------------------------------------------------------------
extern "C" void kernel_launch(void* const* d_in, const int* in_sizes, int n_in,
                              void* d_out, int out_size)
{
    (void)in_sizes; (void)n_in; (void)out_size;
    const float* x  = (const float*)d_in[0];
    const float* Wq = (const float*)d_in[1];
    const float* bq = (const float*)d_in[2];
    const float* Wk = (const float*)d_in[3];
    const float* bk = (const float*)d_in[4];
    const float* Wv = (const float*)d_in[5];
    const float* bv = (const float*)d_in[6];
    float* out = (float*)d_out;

    __half *xh, *xl, *Wth, *Wtl, *Qh, *Ql, *Kh, *Kl, *Vth, *Vtl, *Ph, *Pl;
    float *Vf, *Sc;
    cudaGetSymbolAddress((void**)&xh,  g_xh);  cudaGetSymbolAddress((void**)&xl,  g_xl);
    cudaGetSymbolAddress((void**)&Wth, g_Wth); cudaGetSymbolAddress((void**)&Wtl, g_Wtl);
    cudaGetSymbolAddress((void**)&Qh,  g_Qh);  cudaGetSymbolAddress((void**)&Ql,  g_Ql);
    cudaGetSymbolAddress((void**)&Kh,  g_Kh);  cudaGetSymbolAddress((void**)&Kl,  g_Kl);
    cudaGetSymbolAddress((void**)&Vf,  g_Vf);
    cudaGetSymbolAddress((void**)&Vth, g_Vth); cudaGetSymbolAddress((void**)&Vtl, g_Vtl);
    cudaGetSymbolAddress((void**)&Sc,  g_S);
    cudaGetSymbolAddress((void**)&Ph,  g_Ph);  cudaGetSymbolAddress((void**)&Pl,  g_Pl);

    cudaFuncSetAttribute(gemm_mma<0>, cudaFuncAttributeMaxDynamicSharedMemorySize, SMEMB);
    cudaFuncSetAttribute(gemm_mma<1>, cudaFuncAttributeMaxDynamicSharedMemorySize, SMEMB);

    const float scale = 1.0f / sqrtf((float)DD);

    // 1) split x into hi/lo fp16
    {
        int n4 = MTOT * DD / 4;
        split_f32<<<(n4 + 255) / 256, 256>>>(x, xh, xl, n4);
    }
    // 2) transpose+split weights: Wt[n][k] = W[k][n]
    {
        dim3 tb(32, 8), tg(DD/32, DD/32, 1);
        transpose_split<<<tg, tb>>>(Wq, Wth + 0*DD*DD, Wtl + 0*DD*DD, DD, DD, 0, 0);
        transpose_split<<<tg, tb>>>(Wk, Wth + 1*DD*DD, Wtl + 1*DD*DD, DD, DD, 0, 0);
        transpose_split<<<tg, tb>>>(Wv, Wth + 2*DD*DD, Wtl + 2*DD*DD, DD, DD, 0, 0);
    }
    // 3) projections (M=16384, N=512, K=512)
    {
        dim3 g(DD/128, MTOT/128, 1);
        gemm_mma<1><<<g, 256, SMEMB>>>(xh, xl, Wth + 0*DD*DD, Wtl + 0*DD*DD, bq,
                                       nullptr, Qh, Ql, DD, DD, 1.0f, 0, 0, 0);
        gemm_mma<1><<<g, 256, SMEMB>>>(xh, xl, Wth + 1*DD*DD, Wtl + 1*DD*DD, bk,
                                       nullptr, Kh, Kl, DD, DD, 1.0f, 0, 0, 0);
        gemm_mma<0><<<g, 256, SMEMB>>>(xh, xl, Wth + 2*DD*DD, Wtl + 2*DD*DD, bv,
                                       Vf, nullptr, nullptr, DD, DD, 1.0f, 0, 0, 0);
    }
    // 4) transpose+split V per batch: Vf [s,e] -> Vt [e,s]
    {
        dim3 tb(32, 8), tg(DD/32, SS/32, BB);
        transpose_split<<<tg, tb>>>(Vf, Vth, Vtl, SS, DD,
                                    (long long)SS*DD, (long long)DD*SS);
    }
    // 5) scores = scale * Q @ K^T per batch (M=N=2048, K=512)
    {
        dim3 g(SS/128, SS/128, BB);
        gemm_mma<0><<<g, 256, SMEMB>>>(Qh, Ql, Kh, Kl, nullptr,
                                       Sc, nullptr, nullptr, SS, DD, scale,
                                       (long long)SS*DD, (long long)SS*DD,
                                       (long long)SS*SS);
    }
    // 6) softmax -> P hi/lo
    softmax2048<<<BB*SS, 256>>>(Sc, Ph, Pl);
    // 7) out = P @ V per batch (M=2048, N=512, K=2048)
    {
        dim3 g(DD/128, SS/128, BB);
        gemm_mma<0><<<g, 256, SMEMB>>>(Ph, Pl, Vth, Vtl, nullptr,
                                       out, nullptr, nullptr, DD, SS, 1.0f,
                                       (long long)SS*SS, (long long)DD*SS,
                                       (long long)SS*DD);
    }
}

// round 4
// speedup vs baseline: 2.7700x; 1.2752x over previous
#include <cuda_runtime.h>
#include <cuda_fp16.h>
#include <math.h>
#include <stdint.h>

#define BB 8
#define SS 2048
#define DD 512
#define MTOT (BB*SS)

// ---------------- device scratch (no runtime allocation allowed) ------------
__device__ __half g_xh[MTOT*DD], g_xl[MTOT*DD];
__device__ __half g_Wth[3][DD*DD], g_Wtl[3][DD*DD];
__device__ __half g_Qh[MTOT*DD];
__device__ __half g_Kh[MTOT*DD], g_Kl[MTOT*DD];
__device__ float  g_Vf[MTOT*DD];
__device__ __half g_Vth[MTOT*DD], g_Vtl[MTOT*DD];
__device__ float  g_S [(long long)BB*SS*SS];
__device__ __half g_Ph[(long long)BB*SS*SS];

// ---------------- helpers ----------------------------------------------------
__device__ __forceinline__ uint32_t smem_u32(const void* p){
    uint32_t a;
    asm("{ .reg .u64 t; cvta.to.shared.u64 t, %1; cvt.u32.u64 %0, t; }" : "=r"(a) : "l"(p));
    return a;
}
__device__ __forceinline__ void cpa16(uint32_t dst, const void* src){
    asm volatile("cp.async.cg.shared.global [%0], [%1], 16;" :: "r"(dst), "l"(src));
}
__device__ __forceinline__ void cpa_commit(){ asm volatile("cp.async.commit_group;"); }
template<int N> __device__ __forceinline__ void cpa_wait(){
    asm volatile("cp.async.wait_group %0;" :: "n"(N));
}
__device__ __forceinline__ void ldm_x4(uint32_t* r, uint32_t addr){
    asm volatile("ldmatrix.sync.aligned.m8n8.x4.shared.b16 {%0,%1,%2,%3}, [%4];"
        : "=r"(r[0]), "=r"(r[1]), "=r"(r[2]), "=r"(r[3]) : "r"(addr));
}
__device__ __forceinline__ void mma16816(float* d, const uint32_t* a, uint32_t b0, uint32_t b1){
    asm volatile("mma.sync.aligned.m16n8k16.row.col.f32.f16.f16.f32 "
        "{%0,%1,%2,%3},{%4,%5,%6,%7},{%8,%9},{%0,%1,%2,%3};"
        : "+f"(d[0]), "+f"(d[1]), "+f"(d[2]), "+f"(d[3])
        : "r"(a[0]), "r"(a[1]), "r"(a[2]), "r"(a[3]), "r"(b0), "r"(b1));
}

// ---------------- smem layout -------------------------------------------------
// Per matrix block: 128 rows x 80 bytes (64B data + 16B pad) -> conflict-free ldmatrix.
#define PITCH   80
#define MATB    (128*PITCH)      // 10240 bytes

// ---------------- split-fp16 tensor-core GEMM ---------------------------------
// ASPLIT=1: C = (Ah+Al)*(Bh+Bl)^T, 3-term (hh + hl + lh)
// ASPLIT=0: C =  Ah    *(Bh+Bl)^T, 2-term (hh + hl)         [A already plain fp16]
// A:[M,K] K-major, B:[N,K] K-major. 256 threads, 8 warps, warp tile 64x32.
// EPI 0: Cf = alpha*D + bias (fp32)
// EPI 1: (Ch,Cl) = split(D + bias)  (fp16 hi/lo)
// EPI 2: Ch = fp16(D + bias)        (hi only)
template<int ASPLIT, int EPI>
__global__ void __launch_bounds__(256)
gemm_mma(const __half* __restrict__ Ah, const __half* __restrict__ Al,
         const __half* __restrict__ Bh, const __half* __restrict__ Bl,
         const float* __restrict__ bias,
         float* __restrict__ Cf, __half* __restrict__ Ch, __half* __restrict__ Cl,
         int N, int K, float alpha,
         long long sA, long long sB, long long sC)
{
    constexpr int NMAT   = 3 + ASPLIT;
    constexpr uint32_t STAGEB = NMAT * MATB;

    extern __shared__ char smem[];
    const uint32_t sb = smem_u32(smem);
    const int tid = threadIdx.x;
    const int wid = tid >> 5, lane = tid & 31;
    const int wr = wid >> 2, wc = wid & 3;          // warp grid 2x4
    const int wm0 = wr * 64, wn0 = wc * 32;

    const int row0 = blockIdx.y << 7, col0 = blockIdx.x << 7;
    const long long zA = (long long)blockIdx.z * sA;
    const long long zB = (long long)blockIdx.z * sB;
    const long long zC = (long long)blockIdx.z * sC;

    const __half* gsrc[NMAT];
    {
        int m = 0;
        gsrc[m++] = Ah + zA + (long long)row0 * K;
        if (ASPLIT) gsrc[m++] = Al + zA + (long long)row0 * K;
        gsrc[m++] = Bh + zB + (long long)col0 * K;
        gsrc[m++] = Bl + zB + (long long)col0 * K;
    }

    // loader: per matrix 128 rows x 4 x 16B units = 512 slots, 2 iters of 256 threads
    const int lrow0 = tid >> 2;          // 0..63
    const int lu    = tid & 3;           // 16B unit

    float acc[4][4][4];
#pragma unroll
    for (int i = 0; i < 4; i++)
#pragma unroll
        for (int j = 0; j < 4; j++)
#pragma unroll
            for (int q = 0; q < 4; q++) acc[i][j][q] = 0.0f;

    const int NC = K >> 5;   // chunks of 32

    auto load_chunk = [&](int stage, int kc) {
        const uint32_t sdst = sb + stage * STAGEB;
#pragma unroll
        for (int m = 0; m < NMAT; m++) {
            const __half* g = gsrc[m] + kc * 32;
#pragma unroll
            for (int it = 0; it < 2; it++) {
                const int row = lrow0 + it * 64;
                cpa16(sdst + m * MATB + row * PITCH + lu * 16,
                      g + (long long)row * K + lu * 8);
            }
        }
    };

    load_chunk(0, 0);
    cpa_commit();

    for (int kc = 0; kc < NC; kc++) {
        const int s = kc & 1;
        if (kc + 1 < NC) { load_chunk(s ^ 1, kc + 1); cpa_commit(); cpa_wait<1>(); }
        else             { cpa_wait<0>(); }
        __syncthreads();

        const uint32_t sAh = sb + s * STAGEB;
        const uint32_t sAl = sAh + MATB;                    // valid iff ASPLIT
        const uint32_t sBh = sAh + (1 + ASPLIT) * MATB;
        const uint32_t sBl = sAh + (2 + ASPLIT) * MATB;

        const int lr = lane & 15;            // ldmatrix row-in-tile
        const int lc = (lane >> 4) * 16;     // k8 select (byte offset)

#pragma unroll
        for (int k16 = 0; k16 < 2; k16++) {
            const uint32_t kb = k16 * 32 + lc;
            uint32_t ah[4][4], al[4][4], bh[2][4], bl[2][4];
#pragma unroll
            for (int i = 0; i < 4; i++) {
                const uint32_t ro = (uint32_t)(wm0 + i * 16 + lr) * PITCH + kb;
                ldm_x4(ah[i], sAh + ro);
                if (ASPLIT) ldm_x4(al[i], sAl + ro);
            }
#pragma unroll
            for (int jj = 0; jj < 2; jj++) {
                const uint32_t ro = (uint32_t)(wn0 + jj * 16 + lr) * PITCH + kb;
                ldm_x4(bh[jj], sBh + ro);
                ldm_x4(bl[jj], sBl + ro);
            }
#pragma unroll
            for (int i = 0; i < 4; i++) {
#pragma unroll
                for (int j = 0; j < 4; j++) {
                    const int jj = j >> 1, sel = j & 1;
                    mma16816(acc[i][j], ah[i], bh[jj][sel], bh[jj][sel + 2]);
                    mma16816(acc[i][j], ah[i], bl[jj][sel], bl[jj][sel + 2]);
                    if (ASPLIT)
                        mma16816(acc[i][j], al[i], bh[jj][sel], bh[jj][sel + 2]);
                }
            }
        }
        __syncthreads();
    }

    // ---------------- epilogue ----------------
    const int er = lane >> 2;            // 0..7
    const int ec = (lane & 3) * 2;       // 0,2,4,6
#pragma unroll
    for (int i = 0; i < 4; i++) {
#pragma unroll
        for (int j = 0; j < 4; j++) {
            const int col = col0 + wn0 + j * 8 + ec;
#pragma unroll
            for (int half_m = 0; half_m < 2; half_m++) {
                const int row = row0 + wm0 + i * 16 + er + half_m * 8;
                const float d0 = acc[i][j][half_m * 2 + 0];
                const float d1 = acc[i][j][half_m * 2 + 1];
                if (EPI == 0) {
                    float2 v;
                    v.x = d0 * alpha; v.y = d1 * alpha;
                    if (bias) { v.x += bias[col]; v.y += bias[col + 1]; }
                    *(float2*)(Cf + zC + (long long)row * N + col) = v;
                } else if (EPI == 1) {
                    float f0 = d0 + bias[col];
                    float f1 = d1 + bias[col + 1];
                    __half h0 = __float2half_rn(f0), h1 = __float2half_rn(f1);
                    __half l0 = __float2half_rn(f0 - __half2float(h0));
                    __half l1 = __float2half_rn(f1 - __half2float(h1));
                    *(__half2*)(Ch + zC + (long long)row * N + col) = __halves2half2(h0, h1);
                    *(__half2*)(Cl + zC + (long long)row * N + col) = __halves2half2(l0, l1);
                } else {
                    float f0 = d0 + bias[col];
                    float f1 = d1 + bias[col + 1];
                    *(__half2*)(Ch + zC + (long long)row * N + col) =
                        __halves2half2(__float2half_rn(f0), __float2half_rn(f1));
                }
            }
        }
    }
}

// ---------------- elementwise split fp32 -> (hi,lo) fp16 ---------------------
__global__ void __launch_bounds__(256)
split_f32(const float* __restrict__ s, __half* __restrict__ h, __half* __restrict__ l, int n4)
{
    int i = blockIdx.x * 256 + threadIdx.x;
    if (i >= n4) return;
    float4 v = ((const float4*)s)[i];
    float f[4] = {v.x, v.y, v.z, v.w};
    __half hh[4], ll[4];
#pragma unroll
    for (int j = 0; j < 4; j++) {
        hh[j] = __float2half_rn(f[j]);
        ll[j] = __float2half_rn(f[j] - __half2float(hh[j]));
    }
    *(__half2*)(h + 4*i)     = __halves2half2(hh[0], hh[1]);
    *(__half2*)(h + 4*i + 2) = __halves2half2(hh[2], hh[3]);
    *(__half2*)(l + 4*i)     = __halves2half2(ll[0], ll[1]);
    *(__half2*)(l + 4*i + 2) = __halves2half2(ll[2], ll[3]);
}

// ---------------- transpose + split: src fp32 [R,C] -> dst (hi,lo) [C,R] -----
__global__ void __launch_bounds__(256)
transpose_split(const float* __restrict__ src, __half* __restrict__ dh, __half* __restrict__ dl,
                int R, int C, long long sS, long long sD)
{
    __shared__ float t[32][33];
    const float* S = src + (long long)blockIdx.z * sS;
    __half* DH = dh + (long long)blockIdx.z * sD;
    __half* DL = dl + (long long)blockIdx.z * sD;
    const int c0 = blockIdx.x * 32, r0 = blockIdx.y * 32;
    const int tx = threadIdx.x, ty = threadIdx.y;   // (32, 8)
#pragma unroll
    for (int k = 0; k < 4; k++)
        t[ty + 8*k][tx] = S[(long long)(r0 + ty + 8*k) * C + c0 + tx];
    __syncthreads();
#pragma unroll
    for (int k = 0; k < 4; k++) {
        float f = t[tx][ty + 8*k];
        __half h = __float2half_rn(f);
        __half l = __float2half_rn(f - __half2float(h));
        long long o = (long long)(c0 + ty + 8*k) * R + r0 + tx;
        DH[o] = h; DL[o] = l;
    }
}

// ---------------- row softmax (2048 cols), fp32 in -> plain fp16 out ----------
__global__ void __launch_bounds__(256)
softmax2048(const float* __restrict__ S, __half* __restrict__ Ph)
{
    const long long rb = (long long)blockIdx.x * SS;
    const int t = threadIdx.x;
    float v[8];
    float m = -INFINITY;
#pragma unroll
    for (int i = 0; i < 8; i++) { v[i] = S[rb + t + i*256]; m = fmaxf(m, v[i]); }

    __shared__ float red[8];
#pragma unroll
    for (int o = 16; o > 0; o >>= 1) m = fmaxf(m, __shfl_xor_sync(0xffffffffu, m, o));
    if ((t & 31) == 0) red[t >> 5] = m;
    __syncthreads();
    if (t < 32) {
        float mm = (t < 8) ? red[t] : -INFINITY;
#pragma unroll
        for (int o = 4; o > 0; o >>= 1) mm = fmaxf(mm, __shfl_xor_sync(0xffffffffu, mm, o));
        if (t == 0) red[0] = mm;
    }
    __syncthreads();
    m = red[0];
    __syncthreads();

    float sum = 0.0f;
#pragma unroll
    for (int i = 0; i < 8; i++) { v[i] = __expf(v[i] - m); sum += v[i]; }
#pragma unroll
    for (int o = 16; o > 0; o >>= 1) sum += __shfl_xor_sync(0xffffffffu, sum, o);
    if ((t & 31) == 0) red[t >> 5] = sum;
    __syncthreads();
    if (t < 32) {
        float ss = (t < 8) ? red[t] : 0.0f;
#pragma unroll
        for (int o = 4; o > 0; o >>= 1) ss += __shfl_xor_sync(0xffffffffu, ss, o);
        if (t == 0) red[0] = ss;
    }
    __syncthreads();
    const float inv = 1.0f / red[0];

#pragma unroll
    for (int i = 0; i < 8; i++)
        Ph[rb + t + i*256] = __float2half_rn(v[i] * inv);
}

// -----------------------------------------------------------------------------
extern "C" void kernel_launch(void* const* d_in, const int* in_sizes, int n_in,
                              void* d_out, int out_size)
{
    (void)in_sizes; (void)n_in; (void)out_size;
    const float* x  = (const float*)d_in[0];
    const float* Wq = (const float*)d_in[1];
    const float* bq = (const float*)d_in[2];
    const float* Wk = (const float*)d_in[3];
    const float* bk = (const float*)d_in[4];
    const float* Wv = (const float*)d_in[5];
    const float* bv = (const float*)d_in[6];
    float* out = (float*)d_out;

    __half *xh, *xl, *Wth, *Wtl, *Qh, *Kh, *Kl, *Vth, *Vtl, *Ph;
    float *Vf, *Sc;
    cudaGetSymbolAddress((void**)&xh,  g_xh);  cudaGetSymbolAddress((void**)&xl,  g_xl);
    cudaGetSymbolAddress((void**)&Wth, g_Wth); cudaGetSymbolAddress((void**)&Wtl, g_Wtl);
    cudaGetSymbolAddress((void**)&Qh,  g_Qh);
    cudaGetSymbolAddress((void**)&Kh,  g_Kh);  cudaGetSymbolAddress((void**)&Kl,  g_Kl);
    cudaGetSymbolAddress((void**)&Vf,  g_Vf);
    cudaGetSymbolAddress((void**)&Vth, g_Vth); cudaGetSymbolAddress((void**)&Vtl, g_Vtl);
    cudaGetSymbolAddress((void**)&Sc,  g_S);
    cudaGetSymbolAddress((void**)&Ph,  g_Ph);

    const int SMEMB4 = 2 * 4 * MATB;   // 81920 (A split)
    const int SMEMB3 = 2 * 3 * MATB;   // 61440 (A plain)
    cudaFuncSetAttribute(gemm_mma<1,0>, cudaFuncAttributeMaxDynamicSharedMemorySize, SMEMB4);
    cudaFuncSetAttribute(gemm_mma<1,1>, cudaFuncAttributeMaxDynamicSharedMemorySize, SMEMB4);
    cudaFuncSetAttribute(gemm_mma<1,2>, cudaFuncAttributeMaxDynamicSharedMemorySize, SMEMB4);
    cudaFuncSetAttribute(gemm_mma<0,0>, cudaFuncAttributeMaxDynamicSharedMemorySize, SMEMB3);

    const float scale = 1.0f / sqrtf((float)DD);

    // 1) split x into hi/lo fp16
    {
        int n4 = MTOT * DD / 4;
        split_f32<<<(n4 + 255) / 256, 256>>>(x, xh, xl, n4);
    }
    // 2) transpose+split weights: Wt[n][k] = W[k][n]
    {
        dim3 tb(32, 8), tg(DD/32, DD/32, 1);
        transpose_split<<<tg, tb>>>(Wq, Wth + 0*DD*DD, Wtl + 0*DD*DD, DD, DD, 0, 0);
        transpose_split<<<tg, tb>>>(Wk, Wth + 1*DD*DD, Wtl + 1*DD*DD, DD, DD, 0, 0);
        transpose_split<<<tg, tb>>>(Wv, Wth + 2*DD*DD, Wtl + 2*DD*DD, DD, DD, 0, 0);
    }
    // 3) projections (M=16384, N=512, K=512), 3-term
    {
        dim3 g(DD/128, MTOT/128, 1);
        // Q: plain fp16 output (it becomes the un-split A of the scores GEMM)
        gemm_mma<1,2><<<g, 256, SMEMB4>>>(xh, xl, Wth + 0*DD*DD, Wtl + 0*DD*DD, bq,
                                          nullptr, Qh, nullptr, DD, DD, 1.0f, 0, 0, 0);
        // K: hi/lo split output
        gemm_mma<1,1><<<g, 256, SMEMB4>>>(xh, xl, Wth + 1*DD*DD, Wtl + 1*DD*DD, bk,
                                          nullptr, Kh, Kl, DD, DD, 1.0f, 0, 0, 0);
        // V: fp32 output (split happens in the transpose)
        gemm_mma<1,0><<<g, 256, SMEMB4>>>(xh, xl, Wth + 2*DD*DD, Wtl + 2*DD*DD, bv,
                                          Vf, nullptr, nullptr, DD, DD, 1.0f, 0, 0, 0);
    }
    // 4) transpose+split V per batch: Vf [s,e] -> Vt [e,s]
    {
        dim3 tb(32, 8), tg(DD/32, SS/32, BB);
        transpose_split<<<tg, tb>>>(Vf, Vth, Vtl, SS, DD,
                                    (long long)SS*DD, (long long)DD*SS);
    }
    // 5) scores = scale * Q @ K^T per batch (M=N=2048, K=512), 2-term
    {
        dim3 g(SS/128, SS/128, BB);
        gemm_mma<0,0><<<g, 256, SMEMB3>>>(Qh, nullptr, Kh, Kl, nullptr,
                                          Sc, nullptr, nullptr, SS, DD, scale,
                                          (long long)SS*DD, (long long)SS*DD,
                                          (long long)SS*SS);
    }
    // 6) softmax -> P plain fp16
    softmax2048<<<BB*SS, 256>>>(Sc, Ph);
    // 7) out = P @ V per batch (M=2048, N=512, K=2048), 2-term
    {
        dim3 g(DD/128, SS/128, BB);
        gemm_mma<0,0><<<g, 256, SMEMB3>>>(Ph, nullptr, Vth, Vtl, nullptr,
                                          out, nullptr, nullptr, DD, SS, 1.0f,
                                          (long long)SS*SS, (long long)DD*SS,
                                          (long long)SS*DD);
    }
}